// round 2
// baseline (speedup 1.0000x reference)
#include <cuda_runtime.h>

// LSTM: B=4096, T=512, I=1, H=64, O=1. PyTorch gate order (i,f,g,o).
// Strategy: lane = batch element, warp owns 8 hidden units, 32 batches/block,
// w_hh gate-interleaved in shared (broadcast reads), fp32x2 packed FMA
// (Blackwell FFMA2) computing (i,f) and (g,o) gate pairs together.

#define T_LEN 512
#define HID   64
#define BTILE 32
#define NTHREADS 256
#define JPW   8            // hidden units per warp (8 warps * 8 = 64)
#define HSTRIDE 65         // padded row stride (u64 units) for conflict-free LDS.64

typedef unsigned long long ull;

// Packed fp32x2 FMA: acc.{lo,hi} += a.{lo,hi} * b.{lo,hi}
__device__ __forceinline__ void fma2(ull& acc, ull a, ull b) {
    asm("fma.rn.f32x2 %0, %1, %2, %0;" : "+l"(acc) : "l"(a), "l"(b));
}
__device__ __forceinline__ ull pack2(float lo, float hi) {
    ull r; asm("mov.b64 %0, {%1, %2};" : "=l"(r) : "f"(lo), "f"(hi)); return r;
}
__device__ __forceinline__ void unpack2(ull v, float& lo, float& hi) {
    asm("mov.b64 {%0, %1}, %2;" : "=f"(lo), "=f"(hi) : "l"(v));
}
__device__ __forceinline__ float ex2_fast(float x) {
    float y; asm("ex2.approx.f32 %0, %1;" : "=f"(y) : "f"(x)); return y;
}
__device__ __forceinline__ float rcp_fast(float x) {
    float y; asm("rcp.approx.f32 %0, %1;" : "=f"(y) : "f"(x)); return y;
}
// sigmoid(x) = 1 / (1 + 2^(-x*log2e));  accurate to ~1e-6, no NaN paths
__device__ __forceinline__ float sigmoid_fast(float x) {
    float e = ex2_fast(-1.4426950408889634f * x);
    return rcp_fast(1.0f + e);
}
// tanh(x) = 2*sigmoid(2x) - 1  (safe at both infinities, abs err ~2e-7)
__device__ __forceinline__ float tanh_fast(float x) {
    float e = ex2_fast(-2.8853900817779268f * x);
    return fmaf(2.0f, rcp_fast(1.0f + e), -1.0f);
}

// Dynamic shared layout (bytes):
//   Wsh : ulonglong2[64*64]  = 65536   (Wsh[j*64+k] = { pack(Wi,Wf), pack(Wg,Wo) })
//   Hsh : ull[32*65]         = 16640   (Hsh[b*65+k] = pack(h,h))
//   bsh : float4[64]         = 1024    (combined bias per j, gates i,f,g,o)
//   wxsh: float4[64]         = 1024    (w_ih per j, gates i,f,g,o)
#define SMEM_W_OFF   0
#define SMEM_H_OFF   65536
#define SMEM_B_OFF   (65536 + 16640)
#define SMEM_WX_OFF  (65536 + 16640 + 1024)
#define SMEM_BYTES   (65536 + 16640 + 1024 + 1024)

__global__ void __launch_bounds__(NTHREADS, 1)
lstm_kernel(const float* __restrict__ x,
            const float* __restrict__ w_ih,
            const float* __restrict__ w_hh,
            const float* __restrict__ b_ih,
            const float* __restrict__ b_hh,
            const float* __restrict__ w_out,
            const float* __restrict__ b_out,
            float* __restrict__ out)
{
    extern __shared__ __align__(16) unsigned char smem[];
    ulonglong2* Wsh  = (ulonglong2*)(smem + SMEM_W_OFF);
    ull*        Hsh  = (ull*)       (smem + SMEM_H_OFF);
    float4*     bsh  = (float4*)    (smem + SMEM_B_OFF);
    float4*     wxsh = (float4*)    (smem + SMEM_WX_OFF);

    const int tid  = threadIdx.x;
    const int lane = tid & 31;
    const int warp = tid >> 5;
    const int jb   = warp * JPW;
    const int b    = blockIdx.x * BTILE + lane;

    // ---- one-time prep: gate-interleave w_hh into shared ----
    for (int s = tid; s < HID * HID; s += NTHREADS) {
        int j = s >> 6, k = s & 63;
        float wi = w_hh[(0 * HID + j) * HID + k];
        float wf = w_hh[(1 * HID + j) * HID + k];
        float wg = w_hh[(2 * HID + j) * HID + k];
        float wo = w_hh[(3 * HID + j) * HID + k];
        ulonglong2 v; v.x = pack2(wi, wf); v.y = pack2(wg, wo);
        Wsh[s] = v;
    }
    for (int s = tid; s < HID; s += NTHREADS) {
        float4 bv, wv;
        bv.x = b_ih[0 * HID + s] + b_hh[0 * HID + s];
        bv.y = b_ih[1 * HID + s] + b_hh[1 * HID + s];
        bv.z = b_ih[2 * HID + s] + b_hh[2 * HID + s];
        bv.w = b_ih[3 * HID + s] + b_hh[3 * HID + s];
        wv.x = w_ih[0 * HID + s];
        wv.y = w_ih[1 * HID + s];
        wv.z = w_ih[2 * HID + s];
        wv.w = w_ih[3 * HID + s];
        bsh[s] = bv; wxsh[s] = wv;
    }
    for (int s = tid; s < BTILE * HSTRIDE; s += NTHREADS) Hsh[s] = 0ull;
    __syncthreads();

    float c[JPW];
#pragma unroll
    for (int j = 0; j < JPW; ++j) c[j] = 0.0f;

    const float4* x4 = (const float4*)x + ((b * T_LEN) >> 2);
    const ull* hrow = Hsh + lane * HSTRIDE;        // read: full h row of my batch
    ull* hwr = Hsh + lane * HSTRIDE + jb;          // write: my warp's j-range
    const ulonglong2* Wrow = Wsh + jb * HID;       // my warp's 8 rows of W

    for (int t0 = 0; t0 < T_LEN; t0 += 4) {
        float4 xv = x4[t0 >> 2];
        float xts[4] = {xv.x, xv.y, xv.z, xv.w};
#pragma unroll
        for (int tt = 0; tt < 4; ++tt) {
            const float xt = xts[tt];
            ull aif[JPW], ago[JPW];
#pragma unroll
            for (int j = 0; j < JPW; ++j) {
                float4 bj = bsh[jb + j];
                float4 wj = wxsh[jb + j];
                aif[j] = pack2(fmaf(xt, wj.x, bj.x), fmaf(xt, wj.y, bj.y));
                ago[j] = pack2(fmaf(xt, wj.z, bj.z), fmaf(xt, wj.w, bj.w));
            }
            // gates[j,{i,f,g,o}] += sum_k h[k] * W[j][k][.]
#pragma unroll 4
            for (int k = 0; k < HID; ++k) {
                ull h2 = hrow[k];
#pragma unroll
                for (int j = 0; j < JPW; ++j) {
                    ulonglong2 w = Wrow[j * HID + k];
                    fma2(aif[j], h2, w.x);
                    fma2(ago[j], h2, w.y);
                }
            }
            __syncthreads();   // everyone done READING h before it is overwritten
#pragma unroll
            for (int j = 0; j < JPW; ++j) {
                float gi, gf, gg, go;
                unpack2(aif[j], gi, gf);
                unpack2(ago[j], gg, go);
                float ii = sigmoid_fast(gi);
                float ff = sigmoid_fast(gf);
                float g  = tanh_fast(gg);
                float oo = sigmoid_fast(go);
                c[j] = fmaf(ff, c[j], ii * g);
                float h = oo * tanh_fast(c[j]);
                hwr[j] = pack2(h, h);
            }
            __syncthreads();   // h writes visible before next step's reads
        }
    }

    // output: out[b] = h_T[b,:] @ w_out + b_out   (warp 0 only; h is in Hsh)
    if (warp == 0) {
        float acc = b_out[0];
        const float2* hr = (const float2*)(Hsh + lane * HSTRIDE);
#pragma unroll 8
        for (int k = 0; k < HID; ++k)
            acc = fmaf(hr[k].x, w_out[k], acc);
        out[b] = acc;
    }
}

extern "C" void kernel_launch(void* const* d_in, const int* in_sizes, int n_in,
                              void* d_out, int out_size) {
    const float* x     = (const float*)d_in[0];
    const float* w_ih  = (const float*)d_in[1];
    const float* w_hh  = (const float*)d_in[2];
    const float* b_ih  = (const float*)d_in[3];
    const float* b_hh  = (const float*)d_in[4];
    const float* w_out = (const float*)d_in[5];
    const float* b_out = (const float*)d_in[6];
    float* out = (float*)d_out;

    cudaFuncSetAttribute(lstm_kernel,
                         cudaFuncAttributeMaxDynamicSharedMemorySize, SMEM_BYTES);
    lstm_kernel<<<4096 / BTILE, NTHREADS, SMEM_BYTES>>>(
        x, w_ih, w_hh, b_ih, b_hh, w_out, b_out, out);
}